// round 9
// baseline (speedup 1.0000x reference)
#include <cuda_runtime.h>
#include <math.h>
#include <stdint.h>

#define EMB   1024
#define HS    64
#define TSEQ  4096
#define BATCH 4
#define MTOT  (BATCH * TSEQ)   // 16384 rows

#define NQT2   32              // 128-row q tiles per batch
#define CHUNK  8               // kv-tiles (64 rows each) per partial job
#define NJOBS  144             // sum_{q=0}^{31} (q/4+1) jobs per batch
#define NJOBS_T (NJOBS * BATCH)

// Scratch (device globals: allocation-free rule)
__device__ float g_q[MTOT * HS];
__device__ float g_k[MTOT * HS];
__device__ float g_v[MTOT * HS];
// partial O, transposed row-pair layout: [slot][n(64)][rowpair(64)] as u64=(row2rp,row2rp+1)
__device__ unsigned long long g_po[NJOBS_T * 64 * 64];
__device__ float g_pm[NJOBS_T * 128];    // partial row max
__device__ float g_pl[NJOBS_T * 128];    // partial row sum

// ---- packed fp32x2 ops (Blackwell FFMA2 path; exact fp32 per lane) ----
#define FMA2(d, a, b) \
    asm("fma.rn.f32x2 %0, %1, %2, %0;" : "+l"(d) : "l"(a), "l"(b))
#define MUL2(d, a) \
    asm("mul.rn.f32x2 %0, %0, %1;" : "+l"(d) : "l"(a))
#define PACK2(d, x) \
    asm("mov.b64 %0, {%1, %1};" : "=l"(d) : "r"(__float_as_uint(x)))
#define PACKAB(d, x, y) \
    asm("mov.b64 %0, {%1, %2};" : "=l"(d) : "r"(__float_as_uint(x)), "r"(__float_as_uint(y)))
#define UNPACK2(x, y, d) do { \
    unsigned _lo, _hi; \
    asm("mov.b64 {%0, %1}, %2;" : "=r"(_lo), "=r"(_hi) : "l"(d)); \
    (x) = __uint_as_float(_lo); (y) = __uint_as_float(_hi); } while (0)

// ---------------------------------------------------------------------------
// Kernel 1: fused QKV projection (reverted to the R6-measured-best version).
// [q|k|v] = X @ [Wq|Wk|Wv]. BM=64, BN=3x64, BK=32. 128 threads; each thread
// owns 8 rows x (3 x 4 cols) on packed f32x2 accumulators.
// ---------------------------------------------------------------------------
#define XST 33
#define WST 68

__global__ __launch_bounds__(128) void qkv_kernel(
    const float* __restrict__ X,
    const float* __restrict__ Wq,
    const float* __restrict__ Wk,
    const float* __restrict__ Wv)
{
    __shared__ __align__(16) float Xs[64 * XST];       // [row][k]
    __shared__ __align__(16) float Ws[3][32 * WST];    // [w][k][col]

    const int tid = threadIdx.x;
    const int tx = tid & 15;        // col group: cols 4*tx..4*tx+3 (per W)
    const int ty = tid >> 4;        // 0..7 -> rows 8*ty..8*ty+7
    const int m0 = blockIdx.x * 64;

    const int lr8 = tid >> 3;       // 0..15 base row
    const int lc8 = tid & 7;        // 0..7 float4 col group within BK=32
    const int wr  = tid >> 2;       // 0..31 k-row
    const int wc4 = tid & 3;        // 0..3 -> col groups wc4 + 4t

    unsigned long long acc[3][8][2];
#pragma unroll
    for (int w = 0; w < 3; w++)
#pragma unroll
        for (int i = 0; i < 8; i++) { acc[w][i][0] = 0ull; acc[w][i][1] = 0ull; }

    for (int k0 = 0; k0 < EMB; k0 += 32) {
        // X tile 64x32 natural
#pragma unroll
        for (int t = 0; t < 4; t++) {
            int row = lr8 + 16 * t;
            float4 xv = *(const float4*)&X[(size_t)(m0 + row) * EMB + k0 + 4 * lc8];
            Xs[row * XST + 4 * lc8 + 0] = xv.x;
            Xs[row * XST + 4 * lc8 + 1] = xv.y;
            Xs[row * XST + 4 * lc8 + 2] = xv.z;
            Xs[row * XST + 4 * lc8 + 3] = xv.w;
        }
        // W tiles 32x64 each
#pragma unroll
        for (int t = 0; t < 4; t++) {
            int cg = wc4 + 4 * t;    // 0..15
            *(float4*)&Ws[0][wr * WST + 4 * cg] =
                *(const float4*)&Wq[(size_t)(k0 + wr) * HS + 4 * cg];
            *(float4*)&Ws[1][wr * WST + 4 * cg] =
                *(const float4*)&Wk[(size_t)(k0 + wr) * HS + 4 * cg];
            *(float4*)&Ws[2][wr * WST + 4 * cg] =
                *(const float4*)&Wv[(size_t)(k0 + wr) * HS + 4 * cg];
        }
        __syncthreads();

#pragma unroll 4
        for (int kk = 0; kk < 32; kk++) {
            unsigned long long ap[8];
#pragma unroll
            for (int i = 0; i < 8; i++) {
                float a = Xs[(8 * ty + i) * XST + kk];    // broadcast scalar LDS
                PACK2(ap[i], a);
            }
            ulonglong2 b0 = *(const ulonglong2*)&Ws[0][kk * WST + 4 * tx];
            ulonglong2 b1 = *(const ulonglong2*)&Ws[1][kk * WST + 4 * tx];
            ulonglong2 b2 = *(const ulonglong2*)&Ws[2][kk * WST + 4 * tx];
#pragma unroll
            for (int i = 0; i < 8; i++) {
                FMA2(acc[0][i][0], ap[i], b0.x); FMA2(acc[0][i][1], ap[i], b0.y);
                FMA2(acc[1][i][0], ap[i], b1.x); FMA2(acc[1][i][1], ap[i], b1.y);
                FMA2(acc[2][i][0], ap[i], b2.x); FMA2(acc[2][i][1], ap[i], b2.y);
            }
        }
        __syncthreads();
    }

#pragma unroll
    for (int i = 0; i < 8; i++) {
        size_t row = (size_t)(m0 + 8 * ty + i);
        *(ulonglong2*)&g_q[row * HS + 4 * tx] = make_ulonglong2(acc[0][i][0], acc[0][i][1]);
        *(ulonglong2*)&g_k[row * HS + 4 * tx] = make_ulonglong2(acc[1][i][0], acc[1][i][1]);
        *(ulonglong2*)&g_v[row * HS + 4 * tx] = make_ulonglong2(acc[2][i][0], acc[2][i][1]);
    }
}

// ---------------------------------------------------------------------------
// Kernel 2: split-KV flash attention partials. BM=128 q-rows x BN=64 kv-rows
// per inner tile, row-pair packed FFMA2:
//   - Q^T smem [64 h][132 qrow] float : one LDS.128 -> both row-pairs (a-ops)
//   - Kdup smem [64 h][66 j] u64 (x,x): LDS.128 -> 2 dup'd j cols (b-ops)
//   - P^T overlays Kdup region between the barriers; Vdup like Kdup
// 256 threads, 2 blocks/SM (101KB smem each) = 16 warps/SM.
// Thread microtile: rows 4ty..4ty+3 (as 2 row-pairs), cols {16g+2tx+jj}.
// Jobs: per batch, qt2=31..0 (LPT), chunks of CHUNK kv-tiles; 576 blocks.
// ---------------------------------------------------------------------------
#define QTST 132   // float stride Qt/Pt rows
#define KDST 66    // u64 stride Kdup/Vdup rows
#define SM_QT  (64 * QTST * 4)                 // 33792
#define SM_KP  (64 * KDST * 8)                 // 33792 (= 64*QTST*4 for Pt)
#define SM_VD  (64 * KDST * 8)                 // 33792
#define ATTN_SMEM_BYTES (SM_QT + SM_KP + SM_VD) // 101376

__global__ __launch_bounds__(256, 2) void attn_partial_kernel(void)
{
    extern __shared__ __align__(16) char smbase[];
    float* Qt = (float*)smbase;                                   // [64][132]
    unsigned long long* Kd = (unsigned long long*)(smbase + SM_QT); // [64][66]
    float* Pt = (float*)(smbase + SM_QT);                         // overlays Kd
    unsigned long long* Vd = (unsigned long long*)(smbase + SM_QT + SM_KP);

    const int b = blockIdx.x & 3;
    int rem = blockIdx.x >> 2;                 // 0..143, LPT order

    // decode job: qt2 descending, nc(q) = q/4+1 chunks each
    int q = 31;
    for (;;) { int nc = (q >> 2) + 1; if (rem < nc) break; rem -= nc; --q; }
    const int qt2 = q;
    const int c = rem;
    const int kt0 = CHUNK * c;
    const int kt1 = min(CHUNK * c + CHUNK, 2 * qt2 + 2);
    // slot index (consistent with reduce): pre(qt2)+c
    int pre = 0;
    for (int qq = 31; qq > qt2; --qq) pre += (qq >> 2) + 1;
    const int slot = b * NJOBS + pre + c;

    const int tid = threadIdx.x;
    const int tx = tid & 7;
    const int ty = tid >> 3;                   // 0..31 -> rows 4ty..4ty+3

    const float* Qg = g_q + ((size_t)b * TSEQ + qt2 * 128) * HS;
    const float* Kg = g_k + (size_t)b * TSEQ * HS;
    const float* Vg = g_v + (size_t)b * TSEQ * HS;

    // ---- load Q tile (128x64) transposed into Qt ----
    {
        int r  = tid & 127;
        int cb = tid >> 7;                     // 0..1
#pragma unroll
        for (int t = 0; t < 8; t++) {
            int c4 = cb + 2 * t;               // 0..15
            float4 v = *(const float4*)&Qg[(size_t)r * HS + 4 * c4];
            Qt[(4 * c4 + 0) * QTST + r] = v.x;
            Qt[(4 * c4 + 1) * QTST + r] = v.y;
            Qt[(4 * c4 + 2) * QTST + r] = v.z;
            Qt[(4 * c4 + 3) * QTST + r] = v.w;
        }
    }

    float m_[4], l_[4];
    unsigned long long o2[2][8];               // [rowpair p][col c]
#pragma unroll
    for (int i = 0; i < 4; i++) { m_[i] = -1e30f; l_[i] = 0.0f; }
#pragma unroll
    for (int p = 0; p < 2; p++)
#pragma unroll
        for (int cc = 0; cc < 8; cc++) o2[p][cc] = 0ull;

    for (int kt = kt0; kt < kt1; kt++) {
        const float* Kt = Kg + (size_t)kt * 64 * HS;
        const float* Vt = Vg + (size_t)kt * 64 * HS;

        // ---- stage K (transposed+dup) and V (dup) ----
        {
            int r  = tid & 63;
            int cb = tid >> 6;                 // 0..3
#pragma unroll
            for (int t = 0; t < 4; t++) {
                int c4 = cb + 4 * t;           // 0..15
                float4 kv = *(const float4*)&Kt[(size_t)r * HS + 4 * c4];
                unsigned long long d;
                PACK2(d, kv.x); Kd[(4 * c4 + 0) * KDST + r] = d;
                PACK2(d, kv.y); Kd[(4 * c4 + 1) * KDST + r] = d;
                PACK2(d, kv.z); Kd[(4 * c4 + 2) * KDST + r] = d;
                PACK2(d, kv.w); Kd[(4 * c4 + 3) * KDST + r] = d;
                float4 vv = *(const float4*)&Vt[(size_t)r * HS + 4 * c4];
                PACK2(d, vv.x); Vd[r * KDST + 4 * c4 + 0] = d;
                PACK2(d, vv.y); Vd[r * KDST + 4 * c4 + 1] = d;
                PACK2(d, vv.z); Vd[r * KDST + 4 * c4 + 2] = d;
                PACK2(d, vv.w); Vd[r * KDST + 4 * c4 + 3] = d;
            }
        }
        __syncthreads();

        // ---- S = Q @ K^T : 1 LDS.128(a) + 4 LDS.128(b) + 16 FFMA2 per h ----
        unsigned long long s2[2][8];
#pragma unroll
        for (int p = 0; p < 2; p++)
#pragma unroll
            for (int cc = 0; cc < 8; cc++) s2[p][cc] = 0ull;

#pragma unroll 4
        for (int h = 0; h < 64; h++) {
            ulonglong2 aa = *(const ulonglong2*)&Qt[h * QTST + 4 * ty];
            // aa.x = (Q[4ty],Q[4ty+1]) ; aa.y = (Q[4ty+2],Q[4ty+3])
#pragma unroll
            for (int g = 0; g < 4; g++) {
                ulonglong2 bb = *(const ulonglong2*)&Kd[h * KDST + 16 * g + 2 * tx];
                FMA2(s2[0][2 * g + 0], aa.x, bb.x);
                FMA2(s2[0][2 * g + 1], aa.x, bb.y);
                FMA2(s2[1][2 * g + 0], aa.y, bb.x);
                FMA2(s2[1][2 * g + 1], aa.y, bb.y);
            }
        }

        // unpack: s[i][cc], row i = 4ty+i, col n = 16*(cc>>1)+2tx+(cc&1)
        float s[4][8];
#pragma unroll
        for (int cc = 0; cc < 8; cc++) {
            UNPACK2(s[0][cc], s[1][cc], s2[0][cc]);
            UNPACK2(s[2][cc], s[3][cc], s2[1][cc]);
        }

        // ---- causal mask (possible on the last two tiles of the span) ----
        if (kt >= 2 * qt2) {
            int cbase = (kt - 2 * qt2) * 64;
#pragma unroll
            for (int i = 0; i < 4; i++) {
                int rloc = 4 * ty + i;
#pragma unroll
                for (int cc = 0; cc < 8; cc++) {
                    int cloc = cbase + 16 * (cc >> 1) + 2 * tx + (cc & 1);
                    if (cloc > rloc) s[i][cc] = -1e30f;
                }
            }
        }

        // ---- online softmax (rows spread over 8 tx lanes: xor 1,2,4) ----
        float alpha[4];
#pragma unroll
        for (int i = 0; i < 4; i++) {
            float mx = s[i][0];
#pragma unroll
            for (int cc = 1; cc < 8; cc++) mx = fmaxf(mx, s[i][cc]);
#pragma unroll
            for (int off = 1; off < 8; off <<= 1)
                mx = fmaxf(mx, __shfl_xor_sync(0xffffffffu, mx, off));
            float mnew = fmaxf(m_[i], mx);
            alpha[i] = __expf(m_[i] - mnew);
            m_[i] = mnew;
            float ps = 0.0f;
#pragma unroll
            for (int cc = 0; cc < 8; cc++) {
                s[i][cc] = __expf(s[i][cc] - mnew);
                ps += s[i][cc];
            }
#pragma unroll
            for (int off = 1; off < 8; off <<= 1)
                ps += __shfl_xor_sync(0xffffffffu, ps, off);
            l_[i] = l_[i] * alpha[i] + ps;
        }
        {
            unsigned long long al01, al23;
            PACKAB(al01, alpha[0], alpha[1]);
            PACKAB(al23, alpha[2], alpha[3]);
#pragma unroll
            for (int cc = 0; cc < 8; cc++) {
                MUL2(o2[0][cc], al01);
                MUL2(o2[1][cc], al23);
            }
        }

        __syncthreads();   // S-loop reads of Kd done before Pt overwrite

        // ---- publish P transposed into the Kd region ----
#pragma unroll
        for (int cc = 0; cc < 8; cc++) {
            int j = 16 * (cc >> 1) + 2 * tx + (cc & 1);
            unsigned long long d01, d23;
            PACKAB(d01, s[0][cc], s[1][cc]);
            PACKAB(d23, s[2][cc], s[3][cc]);
            *(unsigned long long*)&Pt[j * QTST + 4 * ty]     = d01;
            *(unsigned long long*)&Pt[j * QTST + 4 * ty + 2] = d23;
        }
        __syncthreads();

        // ---- O += P @ V : same movless shape ----
#pragma unroll 4
        for (int j = 0; j < 64; j++) {
            ulonglong2 pp = *(const ulonglong2*)&Pt[j * QTST + 4 * ty];
#pragma unroll
            for (int g = 0; g < 4; g++) {
                ulonglong2 vv = *(const ulonglong2*)&Vd[j * KDST + 16 * g + 2 * tx];
                FMA2(o2[0][2 * g + 0], pp.x, vv.x);
                FMA2(o2[0][2 * g + 1], pp.x, vv.y);
                FMA2(o2[1][2 * g + 0], pp.y, vv.x);
                FMA2(o2[1][2 * g + 1], pp.y, vv.y);
            }
        }
        __syncthreads();   // PV reads of Pt done before next tile's Kd stage
    }

    // ---- write partial: O as u64 row-pairs, transposed [slot][n][rowpair] ----
#pragma unroll
    for (int cc = 0; cc < 8; cc++) {
        int n = 16 * (cc >> 1) + 2 * tx + (cc & 1);
        g_po[((size_t)slot * 64 + n) * 64 + 2 * ty + 0] = o2[0][cc];
        g_po[((size_t)slot * 64 + n) * 64 + 2 * ty + 1] = o2[1][cc];
    }
    if (tx == 0) {
#pragma unroll
        for (int i = 0; i < 4; i++) {
            g_pm[(size_t)slot * 128 + 4 * ty + i] = m_[i];
            g_pl[(size_t)slot * 128 + 4 * ty + i] = l_[i];
        }
    }
}

// ---------------------------------------------------------------------------
// Kernel 3: combine partials (log-sum-exp merge) + epilogue /(l*8).
// Grid (32 qt2, 4 batch), 256 threads: rowpair rp = tid&63 (rows 2rp,2rp+1),
// col group nh = tid>>6 -> n in [16nh, 16nh+16).
// ---------------------------------------------------------------------------
__global__ __launch_bounds__(256) void attn_reduce_kernel(float* __restrict__ out)
{
    const int qt2 = blockIdx.x;
    const int b   = blockIdx.y;
    const int tid = threadIdx.x;
    const int rp  = tid & 63;
    const int n0  = (tid >> 6) * 16;

    const int nc = (qt2 >> 2) + 1;
    int pre = 0;
    for (int qq = 31; qq > qt2; --qq) pre += (qq >> 2) + 1;
    const int gslot = b * NJOBS + pre;

    // pass 1: global row max for both rows of the pair
    float M0 = -1e30f, M1 = -1e30f;
    for (int c = 0; c < nc; c++) {
        M0 = fmaxf(M0, g_pm[(size_t)(gslot + c) * 128 + 2 * rp + 0]);
        M1 = fmaxf(M1, g_pm[(size_t)(gslot + c) * 128 + 2 * rp + 1]);
    }

    float ls0 = 0.0f, ls1 = 0.0f;
    float a0[16], a1[16];
#pragma unroll
    for (int t = 0; t < 16; t++) { a0[t] = 0.0f; a1[t] = 0.0f; }

    for (int c = 0; c < nc; c++) {
        int slot = gslot + c;
        float w0 = __expf(g_pm[(size_t)slot * 128 + 2 * rp + 0] - M0);
        float w1 = __expf(g_pm[(size_t)slot * 128 + 2 * rp + 1] - M1);
        ls0 = fmaf(w0, g_pl[(size_t)slot * 128 + 2 * rp + 0], ls0);
        ls1 = fmaf(w1, g_pl[(size_t)slot * 128 + 2 * rp + 1], ls1);
        const unsigned long long* PO = g_po + (size_t)slot * 64 * 64;
#pragma unroll
        for (int t = 0; t < 16; t++) {
            unsigned long long v = PO[(size_t)(n0 + t) * 64 + rp];
            float lo, hi;
            UNPACK2(lo, hi, v);
            a0[t] = fmaf(w0, lo, a0[t]);
            a1[t] = fmaf(w1, hi, a1[t]);
        }
    }

    // /(l) for softmax, /8 for the reference's post-softmax /sqrt(HS) quirk
    const float inv0 = 1.0f / (ls0 * 8.0f);
    const float inv1 = 1.0f / (ls1 * 8.0f);
    float* O0 = out + ((size_t)b * TSEQ + qt2 * 128 + 2 * rp + 0) * HS + n0;
    float* O1 = out + ((size_t)b * TSEQ + qt2 * 128 + 2 * rp + 1) * HS + n0;
#pragma unroll
    for (int t = 0; t < 16; t++) {
        O0[t] = a0[t] * inv0;
        O1[t] = a1[t] * inv1;
    }
}

// ---------------------------------------------------------------------------
extern "C" void kernel_launch(void* const* d_in, const int* in_sizes, int n_in,
                              void* d_out, int out_size)
{
    const float* X  = (const float*)d_in[0];
    const float* Wq = (const float*)d_in[1];
    const float* Wk = (const float*)d_in[2];
    const float* Wv = (const float*)d_in[3];
    float* out = (float*)d_out;

    (void)in_sizes; (void)n_in; (void)out_size;

    // Fused QKV projection (R6-measured-best): 256 blocks x 128 threads
    qkv_kernel<<<MTOT / 64, 128>>>(X, Wq, Wk, Wv);

    // Flash attention partials: 576 blocks (batch-interleaved LPT), 256 thr
    cudaFuncSetAttribute(attn_partial_kernel,
                         cudaFuncAttributeMaxDynamicSharedMemorySize, ATTN_SMEM_BYTES);
    attn_partial_kernel<<<NJOBS_T, 256, ATTN_SMEM_BYTES>>>();

    // Combine partials + epilogue
    dim3 g3(NQT2, BATCH);
    attn_reduce_kernel<<<g3, 256>>>(out);
}

// round 10
// speedup vs baseline: 1.3062x; 1.3062x over previous
#include <cuda_runtime.h>
#include <math.h>
#include <stdint.h>

#define EMB   1024
#define HS    64
#define TSEQ  4096
#define BATCH 4
#define MTOT  (BATCH * TSEQ)   // 16384 rows

#define NQT2   32              // 128-row q tiles per batch
#define CHUNK  8               // 64-row kv-tiles per partial job
#define NJOBS  144             // sum_{q=0}^{31} (q/4+1)
#define NJOBS_T (NJOBS * BATCH)

// Scratch (device globals: allocation-free rule)
__device__ float g_q[MTOT * HS];
__device__ float g_k[MTOT * HS];
__device__ float g_v[MTOT * HS];
__device__ float g_po[NJOBS_T * 128 * HS];   // partial O [slot][row][64]
__device__ float g_pm[NJOBS_T * 128];        // partial row max
__device__ float g_pl[NJOBS_T * 128];        // partial row sum

// ---- packed fp32x2 ops (Blackwell FFMA2 path; exact fp32 per lane) ----
#define FMA2(d, a, b) \
    asm("fma.rn.f32x2 %0, %1, %2, %0;" : "+l"(d) : "l"(a), "l"(b))
#define MUL2(d, a) \
    asm("mul.rn.f32x2 %0, %0, %1;" : "+l"(d) : "l"(a))
#define PACK2(d, x) \
    asm("mov.b64 %0, {%1, %1};" : "=l"(d) : "r"(__float_as_uint(x)))
#define PACKAB(d, x, y) \
    asm("mov.b64 %0, {%1, %2};" : "=l"(d) : "r"(__float_as_uint(x)), "r"(__float_as_uint(y)))
#define UNPACK2(x, y, d) do { \
    unsigned _lo, _hi; \
    asm("mov.b64 {%0, %1}, %2;" : "=r"(_lo), "=r"(_hi) : "l"(d)); \
    (x) = __uint_as_float(_lo); (y) = __uint_as_float(_hi); } while (0)

// ---------------------------------------------------------------------------
// Kernel 1: fused QKV projection (R6/R9 measured-best, verbatim).
// ---------------------------------------------------------------------------
#define XST 33
#define WST 68

__global__ __launch_bounds__(128) void qkv_kernel(
    const float* __restrict__ X,
    const float* __restrict__ Wq,
    const float* __restrict__ Wk,
    const float* __restrict__ Wv)
{
    __shared__ __align__(16) float Xs[64 * XST];
    __shared__ __align__(16) float Ws[3][32 * WST];

    const int tid = threadIdx.x;
    const int tx = tid & 15;
    const int ty = tid >> 4;
    const int m0 = blockIdx.x * 64;

    const int lr8 = tid >> 3;
    const int lc8 = tid & 7;
    const int wr  = tid >> 2;
    const int wc4 = tid & 3;

    unsigned long long acc[3][8][2];
#pragma unroll
    for (int w = 0; w < 3; w++)
#pragma unroll
        for (int i = 0; i < 8; i++) { acc[w][i][0] = 0ull; acc[w][i][1] = 0ull; }

    for (int k0 = 0; k0 < EMB; k0 += 32) {
#pragma unroll
        for (int t = 0; t < 4; t++) {
            int row = lr8 + 16 * t;
            float4 xv = *(const float4*)&X[(size_t)(m0 + row) * EMB + k0 + 4 * lc8];
            Xs[row * XST + 4 * lc8 + 0] = xv.x;
            Xs[row * XST + 4 * lc8 + 1] = xv.y;
            Xs[row * XST + 4 * lc8 + 2] = xv.z;
            Xs[row * XST + 4 * lc8 + 3] = xv.w;
        }
#pragma unroll
        for (int t = 0; t < 4; t++) {
            int cg = wc4 + 4 * t;
            *(float4*)&Ws[0][wr * WST + 4 * cg] =
                *(const float4*)&Wq[(size_t)(k0 + wr) * HS + 4 * cg];
            *(float4*)&Ws[1][wr * WST + 4 * cg] =
                *(const float4*)&Wk[(size_t)(k0 + wr) * HS + 4 * cg];
            *(float4*)&Ws[2][wr * WST + 4 * cg] =
                *(const float4*)&Wv[(size_t)(k0 + wr) * HS + 4 * cg];
        }
        __syncthreads();

#pragma unroll 4
        for (int kk = 0; kk < 32; kk++) {
            unsigned long long ap[8];
#pragma unroll
            for (int i = 0; i < 8; i++) {
                float a = Xs[(8 * ty + i) * XST + kk];
                PACK2(ap[i], a);
            }
            ulonglong2 b0 = *(const ulonglong2*)&Ws[0][kk * WST + 4 * tx];
            ulonglong2 b1 = *(const ulonglong2*)&Ws[1][kk * WST + 4 * tx];
            ulonglong2 b2 = *(const ulonglong2*)&Ws[2][kk * WST + 4 * tx];
#pragma unroll
            for (int i = 0; i < 8; i++) {
                FMA2(acc[0][i][0], ap[i], b0.x); FMA2(acc[0][i][1], ap[i], b0.y);
                FMA2(acc[1][i][0], ap[i], b1.x); FMA2(acc[1][i][1], ap[i], b1.y);
                FMA2(acc[2][i][0], ap[i], b2.x); FMA2(acc[2][i][1], ap[i], b2.y);
            }
        }
        __syncthreads();
    }

#pragma unroll
    for (int i = 0; i < 8; i++) {
        size_t row = (size_t)(m0 + 8 * ty + i);
        *(ulonglong2*)&g_q[row * HS + 4 * tx] = make_ulonglong2(acc[0][i][0], acc[0][i][1]);
        *(ulonglong2*)&g_k[row * HS + 4 * tx] = make_ulonglong2(acc[1][i][0], acc[1][i][1]);
        *(ulonglong2*)&g_v[row * HS + 4 * tx] = make_ulonglong2(acc[2][i][0], acc[2][i][1]);
    }
}

// ---------------------------------------------------------------------------
// Kernel 2: split-KV flash attention partials. BM=128 q-rows x 64 kv-rows,
// 128 threads, 8x8 microtile. Rows owned interleaved: r_i = ty + 16*i
// (ty=tid>>3) so warp ty-quads hit distinct banks on broadcast a-loads.
// Cols: n(jj) = 32*(jj>>1) + 4*tx + 2*(jj&1) pairs (tx=tid&7), matching
// contiguous-128B LDS.128 b-loads on plain Kst/Vs. a-ops PACK2'd on the fly.
// Inner step: 8 LDS.32 + 8 MOV + 2 LDS.128 + 32 FFMA2 -> FMA-bound 2x over.
// ---------------------------------------------------------------------------
#define QST  68    // float stride Qs/Ps rows
#define VSTR 68    // float stride Vs rows
#define SM_Q (128 * QST * 4)
#define SM_P (128 * QST * 4)
#define SM_K (64 * 64 * 4)
#define SM_V (64 * VSTR * 4)
#define ATTN_SMEM_BYTES (SM_Q + SM_P + SM_K + SM_V)   // 103424

__global__ __launch_bounds__(128, 2) void attn_partial_kernel(void)
{
    extern __shared__ __align__(16) char smbase[];
    float* Qs  = (float*)smbase;                    // [128][QST]
    float* Ps  = Qs + 128 * QST;                    // [128][QST]
    float* Kst = Ps + 128 * QST;                    // [64 h][64 j] transposed
    float* Vs  = Kst + 64 * 64;                     // [64 j][VSTR]

    const int b = blockIdx.x & 3;
    int rem = blockIdx.x >> 2;

    // decode job: q descending (LPT), nc(q) = q/4+1 chunks
    int q = 31;
    for (;;) { int nc = (q >> 2) + 1; if (rem < nc) break; rem -= nc; --q; }
    const int qt2 = q;
    const int c = rem;
    const int kt0 = CHUNK * c;
    const int kt1 = min(CHUNK * c + CHUNK, 2 * qt2 + 2);
    int pre = 0;
    for (int qq = 31; qq > qt2; --qq) pre += (qq >> 2) + 1;
    const int slot = b * NJOBS + pre + c;

    const int tid = threadIdx.x;
    const int tx = tid & 7;
    const int ty = tid >> 3;                        // 0..15

    const float* Qg = g_q + ((size_t)b * TSEQ + qt2 * 128) * HS;
    const float* Kg = g_k + (size_t)b * TSEQ * HS;
    const float* Vg = g_v + (size_t)b * TSEQ * HS;

    // ---- load Q tile (128x64), plain row-major ----
#pragma unroll
    for (int t = 0; t < 16; t++) {
        int idx = tid + 128 * t;
        int row = idx >> 4;
        int c4  = idx & 15;
        float4 v = *(const float4*)&Qg[(size_t)row * HS + 4 * c4];
        *(float4*)&Qs[row * QST + 4 * c4] = v;
    }

    float m_[8], l_[8];
    unsigned long long o2[8][4];
#pragma unroll
    for (int i = 0; i < 8; i++) {
        m_[i] = -1e30f; l_[i] = 0.0f;
#pragma unroll
        for (int jj = 0; jj < 4; jj++) o2[i][jj] = 0ull;
    }

    for (int kt = kt0; kt < kt1; kt++) {
        const float* Kt = Kg + (size_t)kt * 64 * HS;
        const float* Vt = Vg + (size_t)kt * 64 * HS;

        // ---- stage K (transposed) and V (natural) ----
        {
            int r  = tid & 63;
            int cb = tid >> 6;                      // 0..1
#pragma unroll
            for (int t = 0; t < 8; t++) {
                int c4 = cb + 2 * t;                // 0..15
                float4 kv = *(const float4*)&Kt[(size_t)r * HS + 4 * c4];
                Kst[(4 * c4 + 0) * 64 + r] = kv.x;
                Kst[(4 * c4 + 1) * 64 + r] = kv.y;
                Kst[(4 * c4 + 2) * 64 + r] = kv.z;
                Kst[(4 * c4 + 3) * 64 + r] = kv.w;
                float4 vv = *(const float4*)&Vt[(size_t)r * HS + 4 * c4];
                *(float4*)&Vs[r * VSTR + 4 * c4] = vv;
            }
        }
        __syncthreads();

        // ---- S = Q @ K^T ----
        unsigned long long s2[8][4];
#pragma unroll
        for (int i = 0; i < 8; i++)
#pragma unroll
            for (int jj = 0; jj < 4; jj++) s2[i][jj] = 0ull;

#pragma unroll 4
        for (int h = 0; h < 64; h++) {
            ulonglong2 b0 = *(const ulonglong2*)&Kst[h * 64 + 4 * tx];
            ulonglong2 b1 = *(const ulonglong2*)&Kst[h * 64 + 32 + 4 * tx];
            unsigned long long ap[8];
#pragma unroll
            for (int i = 0; i < 8; i++) {
                float av = Qs[(ty + 16 * i) * QST + h];
                PACK2(ap[i], av);
            }
#pragma unroll
            for (int i = 0; i < 8; i++) {
                FMA2(s2[i][0], ap[i], b0.x); FMA2(s2[i][1], ap[i], b0.y);
                FMA2(s2[i][2], ap[i], b1.x); FMA2(s2[i][3], ap[i], b1.y);
            }
        }

        // unpack: s[i][cc], col_loc = 32*(cc>>2) + 4tx + (cc&3)
        float s[8][8];
#pragma unroll
        for (int i = 0; i < 8; i++) {
            UNPACK2(s[i][0], s[i][1], s2[i][0]);
            UNPACK2(s[i][2], s[i][3], s2[i][1]);
            UNPACK2(s[i][4], s[i][5], s2[i][2]);
            UNPACK2(s[i][6], s[i][7], s2[i][3]);
        }

        // ---- causal mask (tiles straddling/above the diagonal) ----
        if (kt >= 2 * qt2) {
            int off = (kt - 2 * qt2) * 64;
#pragma unroll
            for (int i = 0; i < 8; i++) {
                int rl = ty + 16 * i;
#pragma unroll
                for (int cc = 0; cc < 8; cc++) {
                    int cl = off + 32 * (cc >> 2) + 4 * tx + (cc & 3);
                    if (cl > rl) s[i][cc] = -1e30f;
                }
            }
        }

        // ---- online softmax (rows spread over 8 tx lanes: xor 1,2,4) ----
#pragma unroll
        for (int i = 0; i < 8; i++) {
            float mx = s[i][0];
#pragma unroll
            for (int cc = 1; cc < 8; cc++) mx = fmaxf(mx, s[i][cc]);
#pragma unroll
            for (int off = 1; off < 8; off <<= 1)
                mx = fmaxf(mx, __shfl_xor_sync(0xffffffffu, mx, off));
            float mnew = fmaxf(m_[i], mx);
            float alpha = __expf(m_[i] - mnew);
            m_[i] = mnew;
            float ps = 0.0f;
#pragma unroll
            for (int cc = 0; cc < 8; cc++) {
                s[i][cc] = __expf(s[i][cc] - mnew);
                ps += s[i][cc];
            }
#pragma unroll
            for (int off = 1; off < 8; off <<= 1)
                ps += __shfl_xor_sync(0xffffffffu, ps, off);
            l_[i] = l_[i] * alpha + ps;
            unsigned long long al2;
            PACK2(al2, alpha);
            MUL2(o2[i][0], al2); MUL2(o2[i][1], al2);
            MUL2(o2[i][2], al2); MUL2(o2[i][3], al2);
        }

        // ---- publish P (plain, u64 pair stores) ----
#pragma unroll
        for (int i = 0; i < 8; i++) {
            int row = ty + 16 * i;
#pragma unroll
            for (int jj = 0; jj < 4; jj++) {
                int n = 32 * (jj >> 1) + 4 * tx + 2 * (jj & 1);
                unsigned long long d;
                PACKAB(d, s[i][2 * jj], s[i][2 * jj + 1]);
                *(unsigned long long*)&Ps[row * QST + n] = d;
            }
        }
        __syncthreads();

        // ---- O += P @ V ----
#pragma unroll 4
        for (int j = 0; j < 64; j++) {
            ulonglong2 v0 = *(const ulonglong2*)&Vs[j * VSTR + 4 * tx];
            ulonglong2 v1 = *(const ulonglong2*)&Vs[j * VSTR + 32 + 4 * tx];
            unsigned long long pp[8];
#pragma unroll
            for (int i = 0; i < 8; i++) {
                float pv = Ps[(ty + 16 * i) * QST + j];
                PACK2(pp[i], pv);
            }
#pragma unroll
            for (int i = 0; i < 8; i++) {
                FMA2(o2[i][0], pp[i], v0.x); FMA2(o2[i][1], pp[i], v0.y);
                FMA2(o2[i][2], pp[i], v1.x); FMA2(o2[i][3], pp[i], v1.y);
            }
        }
        __syncthreads();   // PV reads done before next tile's staging
    }

    // ---- write partial (unnormalized O, row max, row sum) ----
    float* PO = g_po + (size_t)slot * 128 * HS;
#pragma unroll
    for (int i = 0; i < 8; i++) {
        int row = ty + 16 * i;
#pragma unroll
        for (int jj = 0; jj < 4; jj++) {
            int n = 32 * (jj >> 1) + 4 * tx + 2 * (jj & 1);
            *(unsigned long long*)&PO[(size_t)row * HS + n] = o2[i][jj];
        }
    }
    if (tx == 0) {
#pragma unroll
        for (int i = 0; i < 8; i++) {
            g_pm[(size_t)slot * 128 + ty + 16 * i] = m_[i];
            g_pl[(size_t)slot * 128 + ty + 16 * i] = l_[i];
        }
    }
}

// ---------------------------------------------------------------------------
// Kernel 3: combine partials (log-sum-exp merge) + epilogue /(l*8).
// Grid (32, 4), 256 thr: row = tid>>1, segment (tid&1) -> 32 cols.
// ---------------------------------------------------------------------------
__global__ __launch_bounds__(256) void attn_reduce_kernel(float* __restrict__ out)
{
    const int qt2 = blockIdx.x;
    const int b   = blockIdx.y;
    const int tid = threadIdx.x;
    const int r   = tid >> 1;
    const int n0  = (tid & 1) * 32;

    const int nc = (qt2 >> 2) + 1;
    int pre = 0;
    for (int qq = 31; qq > qt2; --qq) pre += (qq >> 2) + 1;
    const int gslot = b * NJOBS + pre;

    float m = -1e30f;
    for (int c = 0; c < nc; c++)
        m = fmaxf(m, g_pm[(size_t)(gslot + c) * 128 + r]);

    float lsum = 0.0f;
    float acc[32];
#pragma unroll
    for (int t = 0; t < 32; t++) acc[t] = 0.0f;

    for (int c = 0; c < nc; c++) {
        int slot = gslot + c;
        float w = __expf(g_pm[(size_t)slot * 128 + r] - m);
        lsum = fmaf(w, g_pl[(size_t)slot * 128 + r], lsum);
        const float* PO = g_po + ((size_t)slot * 128 + r) * HS + n0;
#pragma unroll
        for (int t = 0; t < 8; t++) {
            float4 v = *(const float4*)&PO[4 * t];
            acc[4 * t + 0] = fmaf(w, v.x, acc[4 * t + 0]);
            acc[4 * t + 1] = fmaf(w, v.y, acc[4 * t + 1]);
            acc[4 * t + 2] = fmaf(w, v.z, acc[4 * t + 2]);
            acc[4 * t + 3] = fmaf(w, v.w, acc[4 * t + 3]);
        }
    }

    // /(l) for softmax, /8 for the reference's post-softmax /sqrt(HS) quirk
    const float inv = 1.0f / (lsum * 8.0f);
    float* O = out + ((size_t)b * TSEQ + qt2 * 128 + r) * HS + n0;
#pragma unroll
    for (int t = 0; t < 8; t++) {
        float4 v = make_float4(acc[4 * t + 0] * inv, acc[4 * t + 1] * inv,
                               acc[4 * t + 2] * inv, acc[4 * t + 3] * inv);
        *(float4*)&O[4 * t] = v;
    }
}

// ---------------------------------------------------------------------------
extern "C" void kernel_launch(void* const* d_in, const int* in_sizes, int n_in,
                              void* d_out, int out_size)
{
    const float* X  = (const float*)d_in[0];
    const float* Wq = (const float*)d_in[1];
    const float* Wk = (const float*)d_in[2];
    const float* Wv = (const float*)d_in[3];
    float* out = (float*)d_out;

    (void)in_sizes; (void)n_in; (void)out_size;

    // Fused QKV projection (measured-best): 256 blocks x 128 threads
    qkv_kernel<<<MTOT / 64, 128>>>(X, Wq, Wk, Wv);

    // Flash attention partials: 576 blocks (batch-interleaved LPT), 128 thr
    cudaFuncSetAttribute(attn_partial_kernel,
                         cudaFuncAttributeMaxDynamicSharedMemorySize, ATTN_SMEM_BYTES);
    attn_partial_kernel<<<NJOBS_T, 128, ATTN_SMEM_BYTES>>>();

    // Combine partials + epilogue
    dim3 g3(NQT2, BATCH);
    attn_reduce_kernel<<<g3, 256>>>(out);
}